// round 13
// baseline (speedup 1.0000x reference)
#include <cuda_runtime.h>
#include <math.h>

#define D 192
#define D3 (D * D * D)
#define S_SAMPLES 96
#define NWARP_PER_BLK 8
#define KW_CONST 1.6925687506f  // sqrt(9/pi)

// Quad image: Q[n] = (v[n], v[n+1], v[n+D], v[n+D+1])  -> full 2x2 (axis1 x axisU)
// patch in one aligned 16B load. 113 MB.
__device__ float4 g_quads[D3];
// Shifted accumulator: g_accO[m] accumulates contributions to voxel m+1 (28.3 MB)
__device__ float g_accO[D3];

static __device__ __forceinline__ void red_add_v2(float* addr, float a, float b) {
    asm volatile("red.global.add.v2.f32 [%0], {%1, %2};"
                 :: "l"(addr), "f"(a), "f"(b) : "memory");
}

static __device__ __forceinline__ int iclamp(int v) {
    return min(max(v, 0), D - 1);
}

// Build quad image + zero both accumulators (grid-stride over D3).
__global__ void prep_kernel(const float* __restrict__ img,
                            float* __restrict__ accE) {
    for (int n = blockIdx.x * blockDim.x + threadIdx.x; n < D3;
         n += gridDim.x * blockDim.x) {
        float v0 = img[n];
        float v1 = img[min(n + 1, D3 - 1)];
        float v2 = img[min(n + D, D3 - 1)];
        float v3 = img[min(n + D + 1, D3 - 1)];
        g_quads[n] = make_float4(v0, v1, v2, v3);
        g_accO[n] = 0.0f;
        accE[n] = 0.0f;
    }
}

// PERM0 (z-set): axes (x,y | z)   PERM1 (x-set): (y,z | x)   PERM2 (y-set): (y,x | z)
// linear index into original volume = (i0*D + i1)*D + iu
template<int PERM>
__global__ void __launch_bounds__(NWARP_PER_BLK * 32, 6)
lor_kernel(const float* __restrict__ lors,
           const float* __restrict__ center,
           const float* __restrict__ size,
           float* __restrict__ accE,
           int n)
{
    int warp = (blockIdx.x * blockDim.x + threadIdx.x) >> 5;
    int lane = threadIdx.x & 31;
    if (warp >= n) return;

    const float* L = lors + (size_t)warp * 6;
    float p1x = L[0], p1y = L[1], p1z = L[2];
    float p2x = L[3], p2y = L[4], p2z = L[5];

    float sx = size[0], sy = size[1], sz = size[2];
    float dx = p2x - p1x, dy = p2y - p1y, dz = p2z - p1z;
    float seg = sqrtf(dx * dx + dy * dy + dz * dz) * (1.0f / (float)S_SAMPLES);

    // voxel-space line: w_a(t) = c_a + t*m_a  (divisions hoisted per warp)
    float ivx = (float)D / sx, ivy = (float)D / sy, ivz = (float)D / sz;
    float cxw = (p1x - (center[0] - 0.5f * sx)) * ivx - 0.5f;
    float cyw = (p1y - (center[1] - 0.5f * sy)) * ivy - 0.5f;
    float czw = (p1z - (center[2] - 0.5f * sz)) * ivz - 0.5f;
    float mxw = dx * ivx, myw = dy * ivy, mzw = dz * ivz;

    float c0, c1, cu, m0, m1, mu;
    if (PERM == 0)      { c0 = cxw; c1 = cyw; cu = czw; m0 = mxw; m1 = myw; mu = mzw; }
    else if (PERM == 1) { c0 = cyw; c1 = czw; cu = cxw; m0 = myw; m1 = mzw; mu = mxw; }
    else                { c0 = cyw; c1 = cxw; cu = czw; m0 = myw; m1 = mxw; mu = mzw; }

    // ============== gather pass: 2 aligned float4 quad loads per sample ==============
    float sum = 0.0f;
    #pragma unroll
    for (int k = 0; k < 3; k++) {
        float t = ((float)(lane + 32 * k) + 0.5f) * (1.0f / (float)S_SAMPLES);
        float w0 = fmaf(t, m0, c0);
        float w1 = fmaf(t, m1, c1);
        float wu = fmaf(t, mu, cu);
        float f0 = floorf(w0), f1 = floorf(w1), fu = floorf(wu);
        int i0 = (int)f0, i1 = (int)f1, iu = (int)fu;
        float r0 = w0 - f0, r1 = w1 - f1, ru = wu - fu;

        // axisU base + masked weights (iu in [-1, D-1])
        int   ilo = max(iu, 0);
        float wlo = (iu >= 0) ? (1.0f - ru) : ru;
        float whi = (iu >= 0 && iu + 1 < D) ? ru : 0.0f;

        // axis1 base + masked weights (same trick: quad row .x/.y = J, .z/.w = J+1)
        int   J   = max(i1, 0);
        float Blo = (i1 >= 0) ? (1.0f - r1) : r1;
        float Bhi = (i1 >= 0 && i1 + 1 < D) ? r1 : 0.0f;

        // axis0 row weights + clamped indices
        float A0 = ((unsigned)i0       < (unsigned)D) ? (1.0f - r0) : 0.0f;
        float A1 = ((unsigned)(i0 + 1) < (unsigned)D) ? r0          : 0.0f;
        int I0 = iclamp(i0), I1 = iclamp(i0 + 1);

        float q0 = Blo * wlo, q1 = Blo * whi, q2 = Bhi * wlo, q3 = Bhi * whi;

        int n0 = (I0 * D + J) * D + ilo;
        int n1 = (I1 * D + J) * D + ilo;
        float4 Qa = g_quads[n0];
        float4 Qb = g_quads[n1];
        sum += A0 * (Qa.x * q0 + Qa.y * q1 + Qa.z * q2 + Qa.w * q3)
             + A1 * (Qb.x * q0 + Qb.y * q1 + Qb.z * q2 + Qb.w * q3);
    }

    #pragma unroll
    for (int off = 16; off > 0; off >>= 1)
        sum += __shfl_xor_sync(0xffffffffu, sum, off);

    float a = seg * KW_CONST;
    float contrib = sum * a * a;

    // ========== scatter pass: exactly one aligned red.v2 per row (R9 scheme) ==========
    // pair base b = max(iu,0): b even -> accE + b (slot m = voxel m)
    //                          b odd  -> g_accO + b - 1 (slot m = voxel m+1)
    #pragma unroll 1
    for (int k = 0; k < 3; k++) {
        float t = ((float)(lane + 32 * k) + 0.5f) * (1.0f / (float)S_SAMPLES);
        float w0 = fmaf(t, m0, c0);
        float w1 = fmaf(t, m1, c1);
        float wu = fmaf(t, mu, cu);
        float f0 = floorf(w0), f1 = floorf(w1), fu = floorf(wu);
        int i0 = (int)f0, i1 = (int)f1, iu = (int)fu;
        float r0 = w0 - f0, r1 = w1 - f1, ru = wu - fu;

        int   b   = max(iu, 0);
        float wlo = ((iu >= 0) ? (1.0f - ru) : ru) * contrib;
        float whi = ((iu >= 0 && iu + 1 < D) ? ru : 0.0f) * contrib;

        float* basep = ((b & 1) == 0) ? (accE + b) : (g_accO + (b - 1));

        float A0 = ((unsigned)i0       < (unsigned)D) ? (1.0f - r0) : 0.0f;
        float A1 = ((unsigned)(i0 + 1) < (unsigned)D) ? r0          : 0.0f;
        float B0 = ((unsigned)i1       < (unsigned)D) ? (1.0f - r1) : 0.0f;
        float B1 = ((unsigned)(i1 + 1) < (unsigned)D) ? r1          : 0.0f;
        int I0 = iclamp(i0), I1 = iclamp(i0 + 1);
        int J0 = iclamp(i1), J1 = iclamp(i1 + 1);

        int rowIdx[4] = { (I0 * D + J0) * D, (I0 * D + J1) * D,
                          (I1 * D + J0) * D, (I1 * D + J1) * D };
        float rowW[4] = { A0 * B0, A0 * B1, A1 * B0, A1 * B1 };

        #pragma unroll
        for (int c = 0; c < 4; c++) {
            float rw = rowW[c];
            red_add_v2(basep + rowIdx[c], rw * wlo, rw * whi);
        }
    }
}

__global__ void finalize_kernel(const float* __restrict__ img,
                                const float* __restrict__ eff,
                                float* __restrict__ out, int n) {
    int i = blockIdx.x * blockDim.x + threadIdx.x;
    if (i < n) {
        float bp = out[i] + ((i > 0) ? g_accO[i - 1] : 0.0f);
        out[i] = img[i] / (eff[i] + 1e-8f) * bp;
    }
}

extern "C" void kernel_launch(void* const* d_in, const int* in_sizes, int n_in,
                              void* d_out, int out_size) {
    const float* image  = (const float*)d_in[0];
    const float* eff    = (const float*)d_in[1];
    const float* center = (const float*)d_in[3];
    const float* size   = (const float*)d_in[4];
    const float* xlors  = (const float*)d_in[5];
    const float* ylors  = (const float*)d_in[6];
    const float* zlors  = (const float*)d_in[7];
    float* out = (float*)d_out;

    int nx = in_sizes[5] / 6;
    int ny = in_sizes[6] / 6;
    int nz = in_sizes[7] / 6;

    prep_kernel<<<2048, 256>>>(image, out);

    const int threads = NWARP_PER_BLK * 32;
    lor_kernel<0><<<(nz + NWARP_PER_BLK - 1) / NWARP_PER_BLK, threads>>>(
        zlors, center, size, out, nz);
    lor_kernel<1><<<(nx + NWARP_PER_BLK - 1) / NWARP_PER_BLK, threads>>>(
        xlors, center, size, out, nx);
    lor_kernel<2><<<(ny + NWARP_PER_BLK - 1) / NWARP_PER_BLK, threads>>>(
        ylors, center, size, out, ny);

    finalize_kernel<<<(out_size + 255) / 256, 256>>>(image, eff, out, out_size);
}

// round 16
// speedup vs baseline: 1.3415x; 1.3415x over previous
#include <cuda_runtime.h>
#include <math.h>

#define D 192
#define D3 (D * D * D)
#define S_SAMPLES 96
#define NWARP_PER_BLK 8
#define KW_CONST 1.6925687506f  // sqrt(9/pi)

// Redundant pair image: pairs[n] = (img[n], img[n+1])  (56.6 MB)
__device__ float2 g_pairs[D3];
// Shifted accumulator: g_accO[m] accumulates contributions to voxel m+1 (28.3 MB)
__device__ float g_accO[D3];

static __device__ __forceinline__ void red_add_v2(float* addr, float a, float b) {
    asm volatile("red.global.add.v2.f32 [%0], {%1, %2};"
                 :: "l"(addr), "f"(a), "f"(b) : "memory");
}

static __device__ __forceinline__ int iclamp(int v) {
    return min(max(v, 0), D - 1);
}

// Build pair image + zero both accumulators (grid-stride).
__global__ void prep_kernel(const float4* __restrict__ img4,
                            const float* __restrict__ img,
                            float4* __restrict__ accE4) {
    int n4 = D3 / 4;
    float4 z = make_float4(0.f, 0.f, 0.f, 0.f);
    for (int i = blockIdx.x * blockDim.x + threadIdx.x; i < n4;
         i += gridDim.x * blockDim.x) {
        float4 a = img4[i];
        float b = img[min(4 * i + 4, D3 - 1)];
        float2* p = g_pairs + 4 * i;
        *reinterpret_cast<float4*>(p)     = make_float4(a.x, a.y, a.y, a.z);
        *reinterpret_cast<float4*>(p + 2) = make_float4(a.z, a.w, a.w, b);
        accE4[i] = z;
        reinterpret_cast<float4*>(g_accO)[i] = z;
    }
}

// Fused kernel for all 3 LOR sets. Per warp: select lors + axis permutation.
// z-set: (x,y | z)   x-set: (y,z | x)   y-set: (y,x | z)
// linear index into original volume = (i0*D + i1)*D + iu
__global__ void __launch_bounds__(NWARP_PER_BLK * 32, 6)
lor_all_kernel(const float* __restrict__ xlors,
               const float* __restrict__ ylors,
               const float* __restrict__ zlors,
               int nx, int ny, int nz,
               const float* __restrict__ center,
               const float* __restrict__ size,
               float* __restrict__ accE)
{
    int warp = (blockIdx.x * blockDim.x + threadIdx.x) >> 5;
    int lane = threadIdx.x & 31;
    int total = nx + ny + nz;
    if (warp >= total) return;

    const float* L;
    int perm;
    if (warp < nz)           { L = zlors + (size_t)warp * 6;             perm = 0; }
    else if (warp < nz + nx) { L = xlors + (size_t)(warp - nz) * 6;      perm = 1; }
    else                     { L = ylors + (size_t)(warp - nz - nx) * 6; perm = 2; }

    float p1x = L[0], p1y = L[1], p1z = L[2];
    float p2x = L[3], p2y = L[4], p2z = L[5];

    float sx = size[0], sy = size[1], sz = size[2];
    float dx = p2x - p1x, dy = p2y - p1y, dz = p2z - p1z;
    float seg = sqrtf(dx * dx + dy * dy + dz * dz) * (1.0f / (float)S_SAMPLES);

    // voxel-space line: w_a(t) = c_a + t*m_a  (divisions hoisted per warp)
    float ivx = (float)D / sx, ivy = (float)D / sy, ivz = (float)D / sz;
    float cxw = (p1x - (center[0] - 0.5f * sx)) * ivx - 0.5f;
    float cyw = (p1y - (center[1] - 0.5f * sy)) * ivy - 0.5f;
    float czw = (p1z - (center[2] - 0.5f * sz)) * ivz - 0.5f;
    float mxw = dx * ivx, myw = dy * ivy, mzw = dz * ivz;

    // permuted (axis0, axis1, axisU) triple
    float c0 = (perm == 0) ? cxw : cyw;
    float m0 = (perm == 0) ? mxw : myw;
    float c1 = (perm == 0) ? cyw : ((perm == 1) ? czw : cxw);
    float m1 = (perm == 0) ? myw : ((perm == 1) ? mzw : mxw);
    float cu = (perm == 1) ? cxw : czw;
    float mu = (perm == 1) ? mxw : mzw;

    // ================= gather pass: 1 aligned float2 load per row =================
    float sum = 0.0f;
    #pragma unroll
    for (int k = 0; k < 3; k++) {
        float t = ((float)(lane + 32 * k) + 0.5f) * (1.0f / (float)S_SAMPLES);
        float w0 = fmaf(t, m0, c0);
        float w1 = fmaf(t, m1, c1);
        float wu = fmaf(t, mu, cu);
        float f0 = floorf(w0), f1 = floorf(w1), fu = floorf(wu);
        int i0 = (int)f0, i1 = (int)f1, iu = (int)fu;
        float r0 = w0 - f0, r1 = w1 - f1, ru = wu - fu;

        // iu in [-1, D-1] by geometry.
        int   ilo = max(iu, 0);
        float wlo = (iu >= 0) ? (1.0f - ru) : ru;
        float whi = (iu >= 0 && iu + 1 < D) ? ru : 0.0f;

        float A0 = ((unsigned)i0       < (unsigned)D) ? (1.0f - r0) : 0.0f;
        float A1 = ((unsigned)(i0 + 1) < (unsigned)D) ? r0          : 0.0f;
        float B0 = ((unsigned)i1       < (unsigned)D) ? (1.0f - r1) : 0.0f;
        float B1 = ((unsigned)(i1 + 1) < (unsigned)D) ? r1          : 0.0f;
        int I0 = iclamp(i0), I1 = iclamp(i0 + 1);
        int J0 = iclamp(i1), J1 = iclamp(i1 + 1);

        int rowIdx[4] = { (I0 * D + J0) * D, (I0 * D + J1) * D,
                          (I1 * D + J0) * D, (I1 * D + J1) * D };
        float rowW[4] = { A0 * B0, A0 * B1, A1 * B0, A1 * B1 };

        #pragma unroll
        for (int c = 0; c < 4; c++) {
            float2 p = g_pairs[rowIdx[c] + ilo];
            sum += rowW[c] * (p.x * wlo + p.y * whi);
        }
    }

    #pragma unroll
    for (int off = 16; off > 0; off >>= 1)
        sum += __shfl_xor_sync(0xffffffffu, sum, off);

    float a = seg * KW_CONST;
    float contrib = sum * a * a;

    // ========== scatter pass: exactly one aligned red.v2 per row (R9 scheme) ==========
    // pair base b = max(iu,0): b even -> accE + b (slot m = voxel m)
    //                          b odd  -> g_accO + b - 1 (slot m = voxel m+1)
    #pragma unroll 1
    for (int k = 0; k < 3; k++) {
        float t = ((float)(lane + 32 * k) + 0.5f) * (1.0f / (float)S_SAMPLES);
        float w0 = fmaf(t, m0, c0);
        float w1 = fmaf(t, m1, c1);
        float wu = fmaf(t, mu, cu);
        float f0 = floorf(w0), f1 = floorf(w1), fu = floorf(wu);
        int i0 = (int)f0, i1 = (int)f1, iu = (int)fu;
        float r0 = w0 - f0, r1 = w1 - f1, ru = wu - fu;

        int   b   = max(iu, 0);
        float wlo = ((iu >= 0) ? (1.0f - ru) : ru) * contrib;
        float whi = ((iu >= 0 && iu + 1 < D) ? ru : 0.0f) * contrib;

        float* basep = ((b & 1) == 0) ? (accE + b) : (g_accO + (b - 1));

        float A0 = ((unsigned)i0       < (unsigned)D) ? (1.0f - r0) : 0.0f;
        float A1 = ((unsigned)(i0 + 1) < (unsigned)D) ? r0          : 0.0f;
        float B0 = ((unsigned)i1       < (unsigned)D) ? (1.0f - r1) : 0.0f;
        float B1 = ((unsigned)(i1 + 1) < (unsigned)D) ? r1          : 0.0f;
        int I0 = iclamp(i0), I1 = iclamp(i0 + 1);
        int J0 = iclamp(i1), J1 = iclamp(i1 + 1);

        int rowIdx[4] = { (I0 * D + J0) * D, (I0 * D + J1) * D,
                          (I1 * D + J0) * D, (I1 * D + J1) * D };
        float rowW[4] = { A0 * B0, A0 * B1, A1 * B0, A1 * B1 };

        #pragma unroll
        for (int c = 0; c < 4; c++) {
            float rw = rowW[c];
            red_add_v2(basep + rowIdx[c], rw * wlo, rw * whi);
        }
    }
}

__global__ void finalize_kernel(const float* __restrict__ img,
                                const float* __restrict__ eff,
                                float* __restrict__ out, int n) {
    int i = blockIdx.x * blockDim.x + threadIdx.x;
    if (i < n) {
        float bp = out[i] + ((i > 0) ? g_accO[i - 1] : 0.0f);
        out[i] = img[i] / (eff[i] + 1e-8f) * bp;
    }
}

extern "C" void kernel_launch(void* const* d_in, const int* in_sizes, int n_in,
                              void* d_out, int out_size) {
    const float* image  = (const float*)d_in[0];
    const float* eff    = (const float*)d_in[1];
    const float* center = (const float*)d_in[3];
    const float* size   = (const float*)d_in[4];
    const float* xlors  = (const float*)d_in[5];
    const float* ylors  = (const float*)d_in[6];
    const float* zlors  = (const float*)d_in[7];
    float* out = (float*)d_out;

    int nx = in_sizes[5] / 6;
    int ny = in_sizes[6] / 6;
    int nz = in_sizes[7] / 6;

    prep_kernel<<<2048, 256>>>((const float4*)image, image, (float4*)out);

    int total_warps = nx + ny + nz;
    int blocks = (total_warps + NWARP_PER_BLK - 1) / NWARP_PER_BLK;
    lor_all_kernel<<<blocks, NWARP_PER_BLK * 32>>>(
        xlors, ylors, zlors, nx, ny, nz, center, size, out);

    finalize_kernel<<<(out_size + 255) / 256, 256>>>(image, eff, out, out_size);
}